// round 1
// baseline (speedup 1.0000x reference)
#include <cuda_runtime.h>
#include <math.h>

// ---------------------------------------------------------------------------
// TransitionLayerAblation: fused GRU-cell over N=100000 rows, G=H=256.
//   gi = x @ Wih^T + bih ; gh = h @ Whh^T + bhh
//   r = sig(gi_r+gh_r); z = sig(gi_z+gh_z); n = tanh(gi_n + r*gh_n)
//   hnew = (1-z)*n + z*h ;  mask = any(divided[m,:]>0)
//   h_new_out = mask ? hnew : 0 ;  output[j] = max over masked m of hnew + tf[j]
// Output layout assumed: [0,256) = output+time_features, [256, 256+N*256) = h_new
// ---------------------------------------------------------------------------

__device__ unsigned g_colmax[256];   // ordered-uint encoded per-column max

__device__ __forceinline__ unsigned enc_f(float f) {
    unsigned u = __float_as_uint(f);
    return (u & 0x80000000u) ? ~u : (u | 0x80000000u);
}
__device__ __forceinline__ float dec_f(unsigned u) {
    unsigned v = (u & 0x80000000u) ? (u & 0x7FFFFFFFu) : ~u;
    return __uint_as_float(v);
}

__global__ void init_kernel() { g_colmax[threadIdx.x] = 0u; }

// Block tile: TM=128 rows x TN=64 cols, 256 threads, 8x4 microtile per thread.
// K chunked by 32 through shared memory; two phases (x/Wih then h/Whh).
__device__ __forceinline__ void do_phase(
    const float* __restrict__ A, const float* __restrict__ W,
    float (&acc_r)[8][4], float (&acc_z)[8][4], float (&acc3)[8][4],
    float (&As)[128][36], float (&Ws)[3][32][68],
    int row0, int j0, int N, int tid, int tx, int ty)
{
    const int lk4 = tid & 7;    // loader k-quad (0..7 -> k offsets 0..28 by 4)
    const int lm  = tid >> 3;   // loader row/col index (0..31)

    for (int kc = 0; kc < 256; kc += 32) {
        __syncthreads();
        // --- load A tile [128 rows x 32 k], row-major with pad 36 ---
        #pragma unroll
        for (int p = 0; p < 4; ++p) {
            int m  = lm + p * 32;
            int gm = row0 + m;
            float4 v = make_float4(0.f, 0.f, 0.f, 0.f);
            if (gm < N) v = *(const float4*)&A[gm * 256 + kc + 4 * lk4];
            *(float4*)&As[m][4 * lk4] = v;
        }
        // --- load 3 weight tiles, transposed to [k][j] with pad 68 ---
        #pragma unroll
        for (int g = 0; g < 3; ++g) {
            const float* Wg = W + (g * 256 + j0) * 256;
            #pragma unroll
            for (int p = 0; p < 2; ++p) {
                int j = lm + p * 32;
                float4 v = *(const float4*)&Wg[j * 256 + kc + 4 * lk4];
                Ws[g][4 * lk4 + 0][j] = v.x;
                Ws[g][4 * lk4 + 1][j] = v.y;
                Ws[g][4 * lk4 + 2][j] = v.z;
                Ws[g][4 * lk4 + 3][j] = v.w;
            }
        }
        __syncthreads();
        // --- compute: 8m x 4j x 3 gate-streams ---
        #pragma unroll
        for (int k = 0; k < 32; ++k) {
            float a[8];
            #pragma unroll
            for (int mm = 0; mm < 8; ++mm) a[mm] = As[ty * 8 + mm][k];
            float4 b0 = *(const float4*)&Ws[0][k][tx * 4];
            float4 b1 = *(const float4*)&Ws[1][k][tx * 4];
            float4 b2 = *(const float4*)&Ws[2][k][tx * 4];
            #pragma unroll
            for (int mm = 0; mm < 8; ++mm) {
                acc_r[mm][0] += a[mm] * b0.x; acc_r[mm][1] += a[mm] * b0.y;
                acc_r[mm][2] += a[mm] * b0.z; acc_r[mm][3] += a[mm] * b0.w;
                acc_z[mm][0] += a[mm] * b1.x; acc_z[mm][1] += a[mm] * b1.y;
                acc_z[mm][2] += a[mm] * b1.z; acc_z[mm][3] += a[mm] * b1.w;
                acc3[mm][0]  += a[mm] * b2.x; acc3[mm][1]  += a[mm] * b2.y;
                acc3[mm][2]  += a[mm] * b2.z; acc3[mm][3]  += a[mm] * b2.w;
            }
        }
    }
}

__global__ __launch_bounds__(256, 1)
void gru_kernel(const float* __restrict__ X, const float* __restrict__ H,
                const int* __restrict__ divided,
                const float* __restrict__ Wih, const float* __restrict__ Whh,
                const float* __restrict__ bih, const float* __restrict__ bhh,
                float* __restrict__ out, int N, int houtoff)
{
    __shared__ float As[128][36];
    __shared__ float Ws[3][32][68];
    __shared__ unsigned char maskS[128];

    const int tid  = threadIdx.x;
    const int tx   = tid & 15;
    const int ty   = tid >> 4;
    const int j0   = blockIdx.x * 64;
    const int row0 = blockIdx.y * 128;

    if (tid < 128) {
        int m = row0 + tid;
        unsigned char msk = 0;
        if (m < N)
            msk = (divided[3 * m] > 0) | (divided[3 * m + 1] > 0) |
                  (divided[3 * m + 2] > 0);
        maskS[tid] = msk;
    }

    float acc_r[8][4] = {}, acc_z[8][4] = {}, acc_in[8][4] = {}, acc_hn[8][4] = {};

    do_phase(X, Wih, acc_r, acc_z, acc_in, As, Ws, row0, j0, N, tid, tx, ty);
    do_phase(H, Whh, acc_r, acc_z, acc_hn, As, Ws, row0, j0, N, tid, tx, ty);

    // --- epilogue: gates, mask, store h_new, per-thread column max ---
    float b_r[4], b_z[4], b_ni[4], b_nh[4];
    #pragma unroll
    for (int jj = 0; jj < 4; ++jj) {
        int j    = j0 + tx * 4 + jj;
        b_r[jj]  = bih[j] + bhh[j];
        b_z[jj]  = bih[256 + j] + bhh[256 + j];
        b_ni[jj] = bih[512 + j];
        b_nh[jj] = bhh[512 + j];
    }

    const float NEG_INF = __int_as_float(0xff800000);
    float cmax[4] = {NEG_INF, NEG_INF, NEG_INF, NEG_INF};

    #pragma unroll
    for (int mm = 0; mm < 8; ++mm) {
        int m = row0 + ty * 8 + mm;
        if (m >= N) continue;
        bool msk = maskS[ty * 8 + mm] != 0;
        float4 hold = *(const float4*)&H[m * 256 + j0 + tx * 4];
        float hv[4] = {hold.x, hold.y, hold.z, hold.w};
        float ov[4];
        #pragma unroll
        for (int jj = 0; jj < 4; ++jj) {
            float r  = 1.f / (1.f + __expf(-(acc_r[mm][jj] + b_r[jj])));
            float z  = 1.f / (1.f + __expf(-(acc_z[mm][jj] + b_z[jj])));
            float nn = tanhf(acc_in[mm][jj] + b_ni[jj] +
                             r * (acc_hn[mm][jj] + b_nh[jj]));
            float hn = (1.f - z) * nn + z * hv[jj];
            ov[jj] = msk ? hn : 0.f;
            if (msk) cmax[jj] = fmaxf(cmax[jj], hn);
        }
        if (houtoff >= 0) {
            float4 o4 = make_float4(ov[0], ov[1], ov[2], ov[3]);
            *(float4*)&out[(size_t)houtoff + (size_t)m * 256 + j0 + tx * 4] = o4;
        }
    }

    // --- block column-max reduction, then one atomic per column ---
    __syncthreads();
    float* sred = &As[0][0];   // reuse: 16 x 64 floats
    #pragma unroll
    for (int jj = 0; jj < 4; ++jj)
        sred[ty * 64 + tx * 4 + jj] = cmax[jj];
    __syncthreads();
    if (tid < 64) {
        float v = sred[tid];
        #pragma unroll
        for (int t = 1; t < 16; ++t) v = fmaxf(v, sred[t * 64 + tid]);
        atomicMax(&g_colmax[j0 + tid], enc_f(v));
    }
}

__global__ void finalize_kernel(const float* __restrict__ interval,
                                const float* __restrict__ tw,
                                const float* __restrict__ tb,
                                float* __restrict__ out)
{
    int j = threadIdx.x;
    float inv = 1.0f / logf(interval[0] + expf(1.0f));
    float tf  = tanhf(inv * tw[j] + tb[j]);
    out[j] = dec_f(g_colmax[j]) + tf;
}

extern "C" void kernel_launch(void* const* d_in, const int* in_sizes, int n_in,
                              void* d_out, int out_size)
{
    // Identify inputs by element count (robust to scalar int inclusion),
    // relying on dict order for ties.
    int i_interval = -1, i_co = -1, i_hid = -1, i_div = -1;
    int i_wih = -1, i_whh = -1, i_bih = -1, i_bhh = -1, i_tw = -1, i_tb = -1;
    int c256 = 0;
    for (int i = 0; i < n_in; ++i) {
        int s = in_sizes[i];
        if (s == 1) {
            if (i_interval < 0) i_interval = i;
        } else if (s == 300000) {
            i_div = i;
        } else if (s == 196608) {
            if (i_wih < 0) i_wih = i; else i_whh = i;
        } else if (s == 768) {
            if (i_bih < 0) i_bih = i; else i_bhh = i;
        } else if (s == 256) {
            ++c256;                       // no_emb, unrelated, time_w, time_b
            if (c256 == 3) i_tw = i;
            else if (c256 == 4) i_tb = i;
        } else if (s > 1000000) {         // 25,600,000: co_embeddings then hidden
            if (i_co < 0) i_co = i; else i_hid = i;
        }
    }

    const float* X   = (const float*)d_in[i_co];
    const float* H   = (const float*)d_in[i_hid];
    const int*   div = (const int*)  d_in[i_div];
    const float* Wih = (const float*)d_in[i_wih];
    const float* Whh = (const float*)d_in[i_whh];
    const float* bih = (const float*)d_in[i_bih];
    const float* bhh = (const float*)d_in[i_bhh];
    const float* itv = (const float*)d_in[i_interval];
    const float* tw  = (const float*)d_in[i_tw];
    const float* tb  = (const float*)d_in[i_tb];
    float* out = (float*)d_out;

    int N = in_sizes[i_co] / 256;
    long long need = 256LL + (long long)N * 256LL;
    int houtoff = ((long long)out_size >= need) ? 256 : -1;

    init_kernel<<<1, 256>>>();
    dim3 grid(4, (N + 127) / 128);
    gru_kernel<<<grid, 256>>>(X, H, div, Wih, Whh, bih, bhh, out, N, houtoff);
    finalize_kernel<<<1, 256>>>(itv, tw, tb, out);
}

// round 2
// speedup vs baseline: 1.2555x; 1.2555x over previous
#include <cuda_runtime.h>
#include <math.h>

// ---------------------------------------------------------------------------
// TransitionLayerAblation: fused GRU-cell over N=100000 rows, G=H=256.
// Round 2: packed fma.rn.f32x2 (FFMA2) inner loop -> 2x fp32 FMA throughput.
// Output layout: [0,256) = output+time_features, [256, 256+N*256) = h_new
// ---------------------------------------------------------------------------

typedef unsigned long long u64;

__device__ unsigned g_colmax[256];   // ordered-uint encoded per-column max

__device__ __forceinline__ unsigned enc_f(float f) {
    unsigned u = __float_as_uint(f);
    return (u & 0x80000000u) ? ~u : (u | 0x80000000u);
}
__device__ __forceinline__ float dec_f(unsigned u) {
    unsigned v = (u & 0x80000000u) ? (u & 0x7FFFFFFFu) : ~u;
    return __uint_as_float(v);
}

__device__ __forceinline__ u64 pack2(float x, float y) {
    u64 r; asm("mov.b64 %0, {%1, %2};" : "=l"(r) : "f"(x), "f"(y)); return r;
}
__device__ __forceinline__ void unpack2(u64 v, float& x, float& y) {
    asm("mov.b64 {%0, %1}, %2;" : "=f"(x), "=f"(y) : "l"(v));
}
__device__ __forceinline__ void fma2(u64& acc, u64 a, u64 b) {
    asm("fma.rn.f32x2 %0, %1, %2, %0;" : "+l"(acc) : "l"(a), "l"(b));
}

__global__ void init_kernel() { g_colmax[threadIdx.x] = 0u; }

// Block tile: TM=128 rows x TN=64 cols, 256 threads, 8x4 microtile per thread
// with the 4-wide j dimension packed into two f32x2 lanes per gate stream.
__device__ __forceinline__ void do_phase(
    const float* __restrict__ A, const float* __restrict__ W,
    u64 (&acc_r)[8][2], u64 (&acc_z)[8][2], u64 (&acc3)[8][2],
    float (&As)[128][36], float (&Ws)[3][32][68],
    int row0, int j0, int N, int tid, int tx, int ty)
{
    const int lk4 = tid & 7;    // loader k-quad (0..7 -> k offsets 0..28 by 4)
    const int lm  = tid >> 3;   // loader row/col index (0..31)

    for (int kc = 0; kc < 256; kc += 32) {
        __syncthreads();
        // --- load A tile [128 rows x 32 k], row-major with pad 36 ---
        #pragma unroll
        for (int p = 0; p < 4; ++p) {
            int m  = lm + p * 32;
            int gm = row0 + m;
            float4 v = make_float4(0.f, 0.f, 0.f, 0.f);
            if (gm < N) v = *(const float4*)&A[gm * 256 + kc + 4 * lk4];
            *(float4*)&As[m][4 * lk4] = v;
        }
        // --- load 3 weight tiles, transposed to [k][j] with pad 68 ---
        #pragma unroll
        for (int g = 0; g < 3; ++g) {
            const float* Wg = W + (g * 256 + j0) * 256;
            #pragma unroll
            for (int p = 0; p < 2; ++p) {
                int j = lm + p * 32;
                float4 v = *(const float4*)&Wg[j * 256 + kc + 4 * lk4];
                Ws[g][4 * lk4 + 0][j] = v.x;
                Ws[g][4 * lk4 + 1][j] = v.y;
                Ws[g][4 * lk4 + 2][j] = v.z;
                Ws[g][4 * lk4 + 3][j] = v.w;
            }
        }
        __syncthreads();
        // --- compute: 8m x (2 x f32x2 j) x 3 gate-streams ---
        #pragma unroll
        for (int k = 0; k < 32; ++k) {
            float a[8];
            #pragma unroll
            for (int mm = 0; mm < 8; ++mm) a[mm] = As[ty * 8 + mm][k];
            // b vectors as packed f32x2 pairs straight from smem (LDS.128)
            ulonglong2 b0 = *(const ulonglong2*)&Ws[0][k][tx * 4];
            ulonglong2 b1 = *(const ulonglong2*)&Ws[1][k][tx * 4];
            ulonglong2 b2 = *(const ulonglong2*)&Ws[2][k][tx * 4];
            #pragma unroll
            for (int mm = 0; mm < 8; ++mm) {
                u64 ap = pack2(a[mm], a[mm]);
                fma2(acc_r[mm][0], ap, b0.x); fma2(acc_r[mm][1], ap, b0.y);
                fma2(acc_z[mm][0], ap, b1.x); fma2(acc_z[mm][1], ap, b1.y);
                fma2(acc3[mm][0],  ap, b2.x); fma2(acc3[mm][1],  ap, b2.y);
            }
        }
    }
}

__global__ __launch_bounds__(256, 1)
void gru_kernel(const float* __restrict__ X, const float* __restrict__ H,
                const int* __restrict__ divided,
                const float* __restrict__ Wih, const float* __restrict__ Whh,
                const float* __restrict__ bih, const float* __restrict__ bhh,
                float* __restrict__ out, int N, int houtoff)
{
    __shared__ float As[128][36];
    __shared__ float Ws[3][32][68];
    __shared__ unsigned char maskS[128];

    const int tid  = threadIdx.x;
    const int tx   = tid & 15;
    const int ty   = tid >> 4;
    const int j0   = blockIdx.x * 64;
    const int row0 = blockIdx.y * 128;

    if (tid < 128) {
        int m = row0 + tid;
        unsigned char msk = 0;
        if (m < N)
            msk = (divided[3 * m] > 0) | (divided[3 * m + 1] > 0) |
                  (divided[3 * m + 2] > 0);
        maskS[tid] = msk;
    }

    u64 acc_r[8][2], acc_z[8][2], acc_in[8][2], acc_hn[8][2];
    #pragma unroll
    for (int mm = 0; mm < 8; ++mm)
        #pragma unroll
        for (int p = 0; p < 2; ++p) {
            acc_r[mm][p] = 0ull; acc_z[mm][p] = 0ull;
            acc_in[mm][p] = 0ull; acc_hn[mm][p] = 0ull;
        }

    do_phase(X, Wih, acc_r, acc_z, acc_in, As, Ws, row0, j0, N, tid, tx, ty);
    do_phase(H, Whh, acc_r, acc_z, acc_hn, As, Ws, row0, j0, N, tid, tx, ty);

    // --- epilogue: gates, mask, store h_new, per-thread column max ---
    float b_r[4], b_z[4], b_ni[4], b_nh[4];
    #pragma unroll
    for (int jj = 0; jj < 4; ++jj) {
        int j    = j0 + tx * 4 + jj;
        b_r[jj]  = bih[j] + bhh[j];
        b_z[jj]  = bih[256 + j] + bhh[256 + j];
        b_ni[jj] = bih[512 + j];
        b_nh[jj] = bhh[512 + j];
    }

    const float NEG_INF = __int_as_float(0xff800000);
    float cmax[4] = {NEG_INF, NEG_INF, NEG_INF, NEG_INF};

    #pragma unroll
    for (int mm = 0; mm < 8; ++mm) {
        int m = row0 + ty * 8 + mm;
        if (m >= N) continue;
        bool msk = maskS[ty * 8 + mm] != 0;
        float4 hold = *(const float4*)&H[m * 256 + j0 + tx * 4];
        float hv[4] = {hold.x, hold.y, hold.z, hold.w};
        float ar[4], az[4], ai[4], ah[4];
        unpack2(acc_r[mm][0],  ar[0], ar[1]); unpack2(acc_r[mm][1],  ar[2], ar[3]);
        unpack2(acc_z[mm][0],  az[0], az[1]); unpack2(acc_z[mm][1],  az[2], az[3]);
        unpack2(acc_in[mm][0], ai[0], ai[1]); unpack2(acc_in[mm][1], ai[2], ai[3]);
        unpack2(acc_hn[mm][0], ah[0], ah[1]); unpack2(acc_hn[mm][1], ah[2], ah[3]);
        float ov[4];
        #pragma unroll
        for (int jj = 0; jj < 4; ++jj) {
            float r  = 1.f / (1.f + __expf(-(ar[jj] + b_r[jj])));
            float z  = 1.f / (1.f + __expf(-(az[jj] + b_z[jj])));
            float nn = tanhf(ai[jj] + b_ni[jj] + r * (ah[jj] + b_nh[jj]));
            float hn = (1.f - z) * nn + z * hv[jj];
            ov[jj] = msk ? hn : 0.f;
            if (msk) cmax[jj] = fmaxf(cmax[jj], hn);
        }
        if (houtoff >= 0) {
            float4 o4 = make_float4(ov[0], ov[1], ov[2], ov[3]);
            *(float4*)&out[(size_t)houtoff + (size_t)m * 256 + j0 + tx * 4] = o4;
        }
    }

    // --- block column-max reduction, then one atomic per column ---
    __syncthreads();
    float* sred = &As[0][0];   // reuse: 16 x 64 floats
    #pragma unroll
    for (int jj = 0; jj < 4; ++jj)
        sred[ty * 64 + tx * 4 + jj] = cmax[jj];
    __syncthreads();
    if (tid < 64) {
        float v = sred[tid];
        #pragma unroll
        for (int t = 1; t < 16; ++t) v = fmaxf(v, sred[t * 64 + tid]);
        atomicMax(&g_colmax[j0 + tid], enc_f(v));
    }
}

__global__ void finalize_kernel(const float* __restrict__ interval,
                                const float* __restrict__ tw,
                                const float* __restrict__ tb,
                                float* __restrict__ out)
{
    int j = threadIdx.x;
    float inv = 1.0f / logf(interval[0] + expf(1.0f));
    float tf  = tanhf(inv * tw[j] + tb[j]);
    out[j] = dec_f(g_colmax[j]) + tf;
}

extern "C" void kernel_launch(void* const* d_in, const int* in_sizes, int n_in,
                              void* d_out, int out_size)
{
    int i_interval = -1, i_co = -1, i_hid = -1, i_div = -1;
    int i_wih = -1, i_whh = -1, i_bih = -1, i_bhh = -1, i_tw = -1, i_tb = -1;
    int c256 = 0;
    for (int i = 0; i < n_in; ++i) {
        int s = in_sizes[i];
        if (s == 1) {
            if (i_interval < 0) i_interval = i;
        } else if (s == 300000) {
            i_div = i;
        } else if (s == 196608) {
            if (i_wih < 0) i_wih = i; else i_whh = i;
        } else if (s == 768) {
            if (i_bih < 0) i_bih = i; else i_bhh = i;
        } else if (s == 256) {
            ++c256;                       // no_emb, unrelated, time_w, time_b
            if (c256 == 3) i_tw = i;
            else if (c256 == 4) i_tb = i;
        } else if (s > 1000000) {         // 25,600,000: co_embeddings then hidden
            if (i_co < 0) i_co = i; else i_hid = i;
        }
    }

    const float* X   = (const float*)d_in[i_co];
    const float* H   = (const float*)d_in[i_hid];
    const int*   div = (const int*)  d_in[i_div];
    const float* Wih = (const float*)d_in[i_wih];
    const float* Whh = (const float*)d_in[i_whh];
    const float* bih = (const float*)d_in[i_bih];
    const float* bhh = (const float*)d_in[i_bhh];
    const float* itv = (const float*)d_in[i_interval];
    const float* tw  = (const float*)d_in[i_tw];
    const float* tb  = (const float*)d_in[i_tb];
    float* out = (float*)d_out;

    int N = in_sizes[i_co] / 256;
    long long need = 256LL + (long long)N * 256LL;
    int houtoff = ((long long)out_size >= need) ? 256 : -1;

    init_kernel<<<1, 256>>>();
    dim3 grid(4, (N + 127) / 128);
    gru_kernel<<<grid, 256>>>(X, H, div, Wih, Whh, bih, bhh, out, N, houtoff);
    finalize_kernel<<<1, 256>>>(itv, tw, tb, out);
}

// round 5
// speedup vs baseline: 1.8888x; 1.5044x over previous
#include <cuda_runtime.h>
#include <math.h>
#include <stdint.h>

// ---------------------------------------------------------------------------
// TransitionLayerAblation via mma.sync bf16 (HMMA) with bf16 hi/lo x3 split.
// One fused GEMM: C[128m x 256n] per CTA-row-block, K=512 ([X | H]).
// Streams (n/64): 0=r, 1=z, 2=gi_n (K<256 only), 3=gh_n (K>=256 only).
// Warp->stream mapping balances SMSP tensor load: stream=(w%4 + 2*(w>>2))%4.
// R5 fix: B tiles are stored [n][k] (n-row-major) -> ldmatrix NON-trans.
// Output layout: [0,256) = output+time_features, [256,256+N*256) = h_new
// ---------------------------------------------------------------------------

typedef unsigned long long u64;

__device__ unsigned g_colmax[256];
__device__ __align__(16) unsigned char g_wpack[192 * 8192];  // 1.5 MB bf16 hi/lo

// ---- helpers ---------------------------------------------------------------
__device__ __forceinline__ unsigned enc_f(float f) {
    unsigned u = __float_as_uint(f);
    return (u & 0x80000000u) ? ~u : (u | 0x80000000u);
}
__device__ __forceinline__ float dec_f(unsigned u) {
    unsigned v = (u & 0x80000000u) ? (u & 0x7FFFFFFFu) : ~u;
    return __uint_as_float(v);
}
__device__ __forceinline__ unsigned short f2bf(float x) {  // rn-even
    unsigned u = __float_as_uint(x);
    return (unsigned short)((u + 0x7FFFu + ((u >> 16) & 1u)) >> 16);
}
__device__ __forceinline__ float bf2f(unsigned short s) {
    return __uint_as_float(((unsigned)s) << 16);
}
__device__ __forceinline__ uint32_t smem_u32(const void* p) {
    uint32_t a;
    asm("{ .reg .u64 t; cvta.to.shared.u64 t, %1; cvt.u32.u64 %0, t; }"
        : "=r"(a) : "l"(p));
    return a;
}
__device__ __forceinline__ void ldsm4(uint32_t a, uint32_t& r0, uint32_t& r1,
                                      uint32_t& r2, uint32_t& r3) {
    asm volatile("ldmatrix.sync.aligned.m8n8.x4.shared.b16 {%0,%1,%2,%3}, [%4];"
                 : "=r"(r0), "=r"(r1), "=r"(r2), "=r"(r3) : "r"(a));
}
__device__ __forceinline__ void mma16816(float* d, const uint32_t* a,
                                         uint32_t b0, uint32_t b1) {
    asm volatile(
        "mma.sync.aligned.m16n8k16.row.col.f32.bf16.bf16.f32 "
        "{%0,%1,%2,%3}, {%4,%5,%6,%7}, {%8,%9}, {%0,%1,%2,%3};"
        : "+f"(d[0]), "+f"(d[1]), "+f"(d[2]), "+f"(d[3])
        : "r"(a[0]), "r"(a[1]), "r"(a[2]), "r"(a[3]), "r"(b0), "r"(b1));
}
__device__ __forceinline__ u64 pack_hi4(float4 v) {
    unsigned short h0 = f2bf(v.x), h1 = f2bf(v.y), h2 = f2bf(v.z), h3 = f2bf(v.w);
    return (u64)h0 | ((u64)h1 << 16) | ((u64)h2 << 32) | ((u64)h3 << 48);
}
__device__ __forceinline__ u64 pack_lo4(float4 v, u64 hi) {
    unsigned short l0 = f2bf(v.x - bf2f((unsigned short)(hi)));
    unsigned short l1 = f2bf(v.y - bf2f((unsigned short)(hi >> 16)));
    unsigned short l2 = f2bf(v.z - bf2f((unsigned short)(hi >> 32)));
    unsigned short l3 = f2bf(v.w - bf2f((unsigned short)(hi >> 48)));
    return (u64)l0 | ((u64)l1 << 16) | ((u64)l2 << 32) | ((u64)l3 << 48);
}

__global__ void init_kernel() { g_colmax[threadIdx.x] = 0u; }

// ---- weight prepack: bf16 hi/lo in 8x8-tile-contiguous (ldmatrix) layout ---
// block b -> (p, g, jb, kc); buffer = g_wpack + idx*8192 (hi 4KB, lo 4KB)
// tile element (n,k): off = ((n>>3)*4 + (k>>3))*128 + (n&7)*16 + (k&7)*2
__global__ void pack_weights(const float* __restrict__ Wih,
                             const float* __restrict__ Whh) {
    int b  = blockIdx.x;              // 0..191
    int p  = b / 96, r = b % 96;
    int g  = r / 32; r %= 32;
    int jb = r / 8;
    int kc = r % 8;
    const float* W = p ? Whh : Wih;
    unsigned char* hiB = g_wpack + (size_t)b * 8192;
    unsigned char* loB = hiB + 4096;

    int t  = threadIdx.x;             // 128 threads
    int n  = t & 63;
    int kh = t >> 6;                  // 0/1 -> k 0-15 / 16-31
    const float* src = W + (size_t)(g * 256 + jb * 64 + n) * 256 + kc * 32 + kh * 16;
    #pragma unroll
    for (int q4 = 0; q4 < 4; ++q4) {
        float4 v = *(const float4*)(src + q4 * 4);
        int ko = kh * 16 + q4 * 4;
        unsigned off = (unsigned)(((n >> 3) * 4 + (ko >> 3)) * 128 +
                                  (n & 7) * 16 + ((ko >> 2) & 1) * 8);
        u64 hi = pack_hi4(v);
        *(u64*)(hiB + off) = hi;
        *(u64*)(loB + off) = pack_lo4(v, hi);
    }
}

// ---- main kernel ------------------------------------------------------------
// smem: [0,1024) bias[4][64] | [1024,1152) mask | [1152,2176) wmax[8][32]
//       [4096, ...) union: stage bufs (2 x 40960) / epilogue tiles (8 x 17408)
#define SMEM_U       4096
#define STAGE_BYTES  40960
#define SMEM_TOTAL   (4096 + 8 * 17408)   // 143360

__global__ __launch_bounds__(256, 1)
void gru_mma_kernel(const float* __restrict__ X, const float* __restrict__ H,
                    const int* __restrict__ divided,
                    const float* __restrict__ bih, const float* __restrict__ bhh,
                    float* __restrict__ out, int N, int houtoff)
{
    extern __shared__ __align__(1024) unsigned char smem[];
    float* biasS = (float*)smem;
    unsigned char* maskS = smem + 1024;
    float* wmaxS = (float*)(smem + 1152);
    unsigned char* Uc = smem + SMEM_U;
    const uint32_t sb = smem_u32(smem);
    const uint32_t Ub = sb + SMEM_U;

    const int tid  = threadIdx.x;
    const int wid  = tid >> 5;
    const int lane = tid & 31;
    const int jb   = blockIdx.x;
    const int j0   = jb * 64;
    const int row0 = blockIdx.y * 128;

    const int mh   = wid >> 2;                       // m-half 0/1
    const int st   = ((wid & 3) + 2 * mh) & 3;       // stream 0..3 (SMSP-balanced)
    const int slot = st < 2 ? st : 2;                // B smem slot
    const int cs   = (st == 3) ? 8 : 0;              // active chunk range
    const int ce   = (st == 2) ? 8 : 16;

    // bias[4][64] + mask
    for (int i = tid; i < 256; i += 256) {
        int s = i >> 6, j = i & 63, jg = j0 + j;
        float v;
        if      (s == 0) v = bih[jg]       + bhh[jg];
        else if (s == 1) v = bih[256 + jg] + bhh[256 + jg];
        else if (s == 2) v = bih[512 + jg];
        else             v = bhh[512 + jg];
        biasS[i] = v;
    }
    if (tid < 128) {
        int m = row0 + tid;
        unsigned char msk = 0;
        if (m < N)
            msk = (divided[3 * m] > 0) | (divided[3 * m + 1] > 0) |
                  (divided[3 * m + 2] > 0);
        maskS[tid] = msk;
    }

    float acc[4][8][4];
    #pragma unroll
    for (int a = 0; a < 4; ++a)
        #pragma unroll
        for (int b = 0; b < 8; ++b)
            #pragma unroll
            for (int q = 0; q < 4; ++q) acc[a][b][q] = 0.f;

    // staging registers
    float4 aregs[8];
    int4   bregs[12];
    const int arow = (wid < 4) ? (wid * 32 + lane) : 0;
    const int arot = (arow >> 3) & 7;
    const int ti   = tid - 128;

    // lane constants for ldmatrix
    const int g8 = lane >> 3, lr = lane & 7;
    const uint32_t laneA = (uint32_t)(((g8 & 1) * 4 + (g8 >> 1)) * 128 + lr * 16);
    const uint32_t laneB = (uint32_t)(((g8 >> 1) * 4 + (g8 & 1)) * 128 + lr * 16);

    // ---- prefetch chunk 0 ----
    {
        const int p = 0, kc = 0;
        if (wid < 4) {
            int gm = row0 + arow;
            const float* src = X + (size_t)gm * 256 + kc * 32;
            #pragma unroll
            for (int qq = 0; qq < 8; ++qq) {
                int q = (qq + arot) & 7;
                aregs[qq] = (gm < N) ? *(const float4*)(src + q * 4)
                                     : make_float4(0.f, 0.f, 0.f, 0.f);
            }
        } else {
            #pragma unroll
            for (int jj = 0; jj < 12; ++jj) {
                int i = jj * 128 + ti;
                int g = i >> 9, sub = i & 511;
                bregs[jj] = *(const int4*)(g_wpack +
                    (size_t)(((p * 3 + g) * 4 + jb) * 8 + kc) * 8192 + sub * 16);
            }
        }
    }

    for (int c = 0; c < 16; ++c) {
        // ---- store staged chunk c into buf[c&1] ----
        if (wid < 4) {
            unsigned char* Ahi = Uc + (c & 1) * STAGE_BYTES;
            unsigned char* Alo = Ahi + 8192;
            int mi = arow >> 3, mr = arow & 7;
            #pragma unroll
            for (int qq = 0; qq < 8; ++qq) {
                int q = (qq + arot) & 7;
                unsigned off = (unsigned)((mi * 4 + (q >> 1)) * 128 +
                                          mr * 16 + (q & 1) * 8);
                u64 hi = pack_hi4(aregs[qq]);
                *(u64*)(Ahi + off) = hi;
                *(u64*)(Alo + off) = pack_lo4(aregs[qq], hi);
            }
        } else {
            unsigned char* Bb = Uc + (c & 1) * STAGE_BYTES + 16384;
            #pragma unroll
            for (int jj = 0; jj < 12; ++jj) {
                int i = jj * 128 + ti;
                int g = i >> 9, sub = i & 511;
                *(int4*)(Bb + g * 8192 + sub * 16) = bregs[jj];
            }
        }
        __syncthreads();

        // ---- prefetch chunk c+1 ----
        if (c < 15) {
            const int cn = c + 1;
            const int p = cn >> 3, kc = cn & 7;
            if (wid < 4) {
                int gm = row0 + arow;
                const float* Ap = p ? H : X;
                const float* src = Ap + (size_t)gm * 256 + kc * 32;
                #pragma unroll
                for (int qq = 0; qq < 8; ++qq) {
                    int q = (qq + arot) & 7;
                    aregs[qq] = (gm < N) ? *(const float4*)(src + q * 4)
                                         : make_float4(0.f, 0.f, 0.f, 0.f);
                }
            } else {
                #pragma unroll
                for (int jj = 0; jj < 12; ++jj) {
                    int i = jj * 128 + ti;
                    int g = i >> 9, sub = i & 511;
                    bregs[jj] = *(const int4*)(g_wpack +
                        (size_t)(((p * 3 + g) * 4 + jb) * 8 + kc) * 8192 + sub * 16);
                }
            }
        }

        // ---- MMA on chunk c ----
        if (c >= cs && c < ce) {
            const uint32_t abh = Ub + (c & 1) * STAGE_BYTES;
            const uint32_t abl = abh + 8192;
            const uint32_t bbh = abh + 16384 + slot * 8192;
            const uint32_t bbl = bbh + 4096;
            #pragma unroll
            for (int ks = 0; ks < 2; ++ks) {
                uint32_t ah[4][4], al[4][4];
                #pragma unroll
                for (int mb = 0; mb < 4; ++mb) {
                    uint32_t off = (uint32_t)((mh * 32 + mb * 8 + ks * 2) * 128);
                    ldsm4(abh + off + laneA, ah[mb][0], ah[mb][1], ah[mb][2], ah[mb][3]);
                    ldsm4(abl + off + laneA, al[mb][0], al[mb][1], al[mb][2], al[mb][3]);
                }
                #pragma unroll
                for (int nb2 = 0; nb2 < 4; ++nb2) {
                    uint32_t offb = (uint32_t)((nb2 * 8 + ks * 2) * 128);
                    uint32_t bh[4], bl[4];
                    // B tiles are [n][k] n-row-major -> NON-trans ldmatrix
                    ldsm4(bbh + offb + laneB, bh[0], bh[1], bh[2], bh[3]);
                    ldsm4(bbl + offb + laneB, bl[0], bl[1], bl[2], bl[3]);
                    #pragma unroll
                    for (int mb = 0; mb < 4; ++mb) {
                        mma16816(acc[mb][nb2 * 2],     ah[mb], bh[0], bh[1]);
                        mma16816(acc[mb][nb2 * 2],     ah[mb], bl[0], bl[1]);
                        mma16816(acc[mb][nb2 * 2],     al[mb], bh[0], bh[1]);
                        mma16816(acc[mb][nb2 * 2 + 1], ah[mb], bh[2], bh[3]);
                        mma16816(acc[mb][nb2 * 2 + 1], ah[mb], bl[2], bl[3]);
                        mma16816(acc[mb][nb2 * 2 + 1], al[mb], bh[2], bh[3]);
                    }
                }
            }
        }
        __syncthreads();
    }

    // ---- epilogue: dump accum tiles to smem (stride 68) ----
    {
        float* Et = (float*)(Uc + (st * 2 + mh) * 17408);
        int r0l = lane >> 2, c0 = (lane & 3) * 2;
        #pragma unroll
        for (int mb = 0; mb < 4; ++mb)
            #pragma unroll
            for (int nb = 0; nb < 8; ++nb) {
                int r = mb * 16 + r0l, cc = nb * 8 + c0;
                *(float2*)&Et[r * 68 + cc] =
                    make_float2(acc[mb][nb][0], acc[mb][nb][1]);
                *(float2*)&Et[(r + 8) * 68 + cc] =
                    make_float2(acc[mb][nb][2], acc[mb][nb][3]);
            }
    }
    __syncthreads();

    // ---- gate math + masked store + column max ----
    {
        const int row = tid & 127, jh = tid >> 7;
        const int gm = row0 + row;
        const bool valid = gm < N;
        const bool msk = valid && maskS[row];
        const int mh2 = row >> 6, lr2 = row & 63;
        const float* Er  = (float*)(Uc + (0 * 2 + mh2) * 17408) + lr2 * 68 + jh * 32;
        const float* Ez  = (float*)(Uc + (1 * 2 + mh2) * 17408) + lr2 * 68 + jh * 32;
        const float* Eni = (float*)(Uc + (2 * 2 + mh2) * 17408) + lr2 * 68 + jh * 32;
        const float* Enh = (float*)(Uc + (3 * 2 + mh2) * 17408) + lr2 * 68 + jh * 32;
        const float NEG_INF = __int_as_float(0xff800000);

        #pragma unroll
        for (int qb = 0; qb < 8; ++qb) {
            float4 rv  = *(const float4*)(Er  + qb * 4);
            float4 zv  = *(const float4*)(Ez  + qb * 4);
            float4 niv = *(const float4*)(Eni + qb * 4);
            float4 nhv = *(const float4*)(Enh + qb * 4);
            float4 h4 = valid
                ? *(const float4*)&H[(size_t)gm * 256 + j0 + jh * 32 + qb * 4]
                : make_float4(0.f, 0.f, 0.f, 0.f);
            float rr[4] = {rv.x, rv.y, rv.z, rv.w};
            float zz[4] = {zv.x, zv.y, zv.z, zv.w};
            float ni[4] = {niv.x, niv.y, niv.z, niv.w};
            float nh[4] = {nhv.x, nhv.y, nhv.z, nhv.w};
            float hh[4] = {h4.x, h4.y, h4.z, h4.w};
            float o[4];
            #pragma unroll
            for (int e = 0; e < 4; ++e) {
                int jl = jh * 32 + qb * 4 + e;
                float r = 1.f / (1.f + __expf(-(rr[e] + biasS[jl])));
                float z = 1.f / (1.f + __expf(-(zz[e] + biasS[64 + jl])));
                float nn = tanhf(ni[e] + biasS[128 + jl] +
                                 r * (nh[e] + biasS[192 + jl]));
                float hn = (1.f - z) * nn + z * hh[e];
                o[e] = msk ? hn : 0.f;
                float mv = msk ? hn : NEG_INF;
                #pragma unroll
                for (int d = 16; d >= 1; d >>= 1)
                    mv = fmaxf(mv, __shfl_xor_sync(0xffffffffu, mv, d));
                if (lane == 0) wmaxS[wid * 32 + qb * 4 + e] = mv;
            }
            if (valid && houtoff >= 0) {
                *(float4*)&out[(size_t)houtoff + (size_t)gm * 256 + j0 +
                               jh * 32 + qb * 4] = make_float4(o[0], o[1], o[2], o[3]);
            }
        }
    }
    __syncthreads();
    if (tid < 64) {
        int jh = tid >> 5, cl = tid & 31;
        float v =        wmaxS[(jh * 4 + 0) * 32 + cl];
        v = fmaxf(v,     wmaxS[(jh * 4 + 1) * 32 + cl]);
        v = fmaxf(v,     wmaxS[(jh * 4 + 2) * 32 + cl]);
        v = fmaxf(v,     wmaxS[(jh * 4 + 3) * 32 + cl]);
        atomicMax(&g_colmax[j0 + jh * 32 + cl], enc_f(v));
    }
}

__global__ void finalize_kernel(const float* __restrict__ interval,
                                const float* __restrict__ tw,
                                const float* __restrict__ tb,
                                float* __restrict__ out)
{
    int j = threadIdx.x;
    float inv = 1.0f / logf(interval[0] + expf(1.0f));
    float tf  = tanhf(inv * tw[j] + tb[j]);
    out[j] = dec_f(g_colmax[j]) + tf;
}

extern "C" void kernel_launch(void* const* d_in, const int* in_sizes, int n_in,
                              void* d_out, int out_size)
{
    int i_interval = -1, i_co = -1, i_hid = -1, i_div = -1;
    int i_wih = -1, i_whh = -1, i_bih = -1, i_bhh = -1, i_tw = -1, i_tb = -1;
    int c256 = 0;
    for (int i = 0; i < n_in; ++i) {
        int s = in_sizes[i];
        if (s == 1) {
            if (i_interval < 0) i_interval = i;
        } else if (s == 300000) {
            i_div = i;
        } else if (s == 196608) {
            if (i_wih < 0) i_wih = i; else i_whh = i;
        } else if (s == 768) {
            if (i_bih < 0) i_bih = i; else i_bhh = i;
        } else if (s == 256) {
            ++c256;                       // no_emb, unrelated, time_w, time_b
            if (c256 == 3) i_tw = i;
            else if (c256 == 4) i_tb = i;
        } else if (s > 1000000) {         // co_embeddings then hidden_state
            if (i_co < 0) i_co = i; else i_hid = i;
        }
    }

    const float* X   = (const float*)d_in[i_co];
    const float* H   = (const float*)d_in[i_hid];
    const int*   div = (const int*)  d_in[i_div];
    const float* Wih = (const float*)d_in[i_wih];
    const float* Whh = (const float*)d_in[i_whh];
    const float* bih = (const float*)d_in[i_bih];
    const float* bhh = (const float*)d_in[i_bhh];
    const float* itv = (const float*)d_in[i_interval];
    const float* tw  = (const float*)d_in[i_tw];
    const float* tb  = (const float*)d_in[i_tb];
    float* out = (float*)d_out;

    int N = in_sizes[i_co] / 256;
    long long need = 256LL + (long long)N * 256LL;
    int houtoff = ((long long)out_size >= need) ? 256 : -1;

    cudaFuncSetAttribute(gru_mma_kernel,
                         cudaFuncAttributeMaxDynamicSharedMemorySize, SMEM_TOTAL);

    init_kernel<<<1, 256>>>();
    pack_weights<<<192, 128>>>(Wih, Whh);
    dim3 grid(4, (N + 127) / 128);
    gru_mma_kernel<<<grid, 256, SMEM_TOTAL>>>(X, H, div, bih, bhh, out, N, houtoff);
    finalize_kernel<<<1, 256>>>(itv, tw, tb, out);
}

// round 6
// speedup vs baseline: 2.2302x; 1.1808x over previous
#include <cuda_runtime.h>
#include <math.h>
#include <stdint.h>

// ---------------------------------------------------------------------------
// TransitionLayerAblation via mma.sync bf16 (HMMA) with bf16 hi/lo x3 split.
// R6: everything pre-packed to bf16 hi/lo in ldmatrix tile layout; main kernel
// is a pure GEMM with a 3-stage cp.async pipeline (no conversion, no staging).
// C[128m x 256n] per CTA-row-block, K=512 ([X | H]).
// Streams (n/64): 0=r, 1=z, 2=gi_n (K<256 only), 3=gh_n (K>=256 only).
// Output layout: [0,256) = output+time_features, [256,256+N*256) = h_new
// ---------------------------------------------------------------------------

typedef unsigned long long u64;

#define RB_MAX 784
__device__ unsigned g_colmax[256];
__device__ __align__(16) unsigned char g_wpack[192 * 8192];          // 1.5 MB
__device__ u64 g_apack[(size_t)2 * RB_MAX * 8 * 2048];               // ~196 MB

// ---- helpers ---------------------------------------------------------------
__device__ __forceinline__ unsigned enc_f(float f) {
    unsigned u = __float_as_uint(f);
    return (u & 0x80000000u) ? ~u : (u | 0x80000000u);
}
__device__ __forceinline__ float dec_f(unsigned u) {
    unsigned v = (u & 0x80000000u) ? (u & 0x7FFFFFFFu) : ~u;
    return __uint_as_float(v);
}
__device__ __forceinline__ unsigned short f2bf(float x) {  // rn-even
    unsigned u = __float_as_uint(x);
    return (unsigned short)((u + 0x7FFFu + ((u >> 16) & 1u)) >> 16);
}
__device__ __forceinline__ float bf2f(unsigned short s) {
    return __uint_as_float(((unsigned)s) << 16);
}
__device__ __forceinline__ uint32_t smem_u32(const void* p) {
    uint32_t a;
    asm("{ .reg .u64 t; cvta.to.shared.u64 t, %1; cvt.u32.u64 %0, t; }"
        : "=r"(a) : "l"(p));
    return a;
}
__device__ __forceinline__ void ldsm4(uint32_t a, uint32_t& r0, uint32_t& r1,
                                      uint32_t& r2, uint32_t& r3) {
    asm volatile("ldmatrix.sync.aligned.m8n8.x4.shared.b16 {%0,%1,%2,%3}, [%4];"
                 : "=r"(r0), "=r"(r1), "=r"(r2), "=r"(r3) : "r"(a));
}
__device__ __forceinline__ void mma16816(float* d, const uint32_t* a,
                                         uint32_t b0, uint32_t b1) {
    asm volatile(
        "mma.sync.aligned.m16n8k16.row.col.f32.bf16.bf16.f32 "
        "{%0,%1,%2,%3}, {%4,%5,%6,%7}, {%8,%9}, {%0,%1,%2,%3};"
        : "+f"(d[0]), "+f"(d[1]), "+f"(d[2]), "+f"(d[3])
        : "r"(a[0]), "r"(a[1]), "r"(a[2]), "r"(a[3]), "r"(b0), "r"(b1));
}
__device__ __forceinline__ void cp16(uint32_t sdst, const void* gsrc) {
    asm volatile("cp.async.cg.shared.global [%0], [%1], 16;"
                 :: "r"(sdst), "l"(gsrc));
}
__device__ __forceinline__ u64 pack_hi4(float4 v) {
    unsigned short h0 = f2bf(v.x), h1 = f2bf(v.y), h2 = f2bf(v.z), h3 = f2bf(v.w);
    return (u64)h0 | ((u64)h1 << 16) | ((u64)h2 << 32) | ((u64)h3 << 48);
}
__device__ __forceinline__ u64 pack_lo4(float4 v, u64 hi) {
    unsigned short l0 = f2bf(v.x - bf2f((unsigned short)(hi)));
    unsigned short l1 = f2bf(v.y - bf2f((unsigned short)(hi >> 16)));
    unsigned short l2 = f2bf(v.z - bf2f((unsigned short)(hi >> 32)));
    unsigned short l3 = f2bf(v.w - bf2f((unsigned short)(hi >> 48)));
    return (u64)l0 | ((u64)l1 << 16) | ((u64)l2 << 32) | ((u64)l3 << 48);
}

__global__ void init_kernel() { g_colmax[threadIdx.x] = 0u; }

// ---- weight prepack (unchanged from R5) ------------------------------------
__global__ void pack_weights(const float* __restrict__ Wih,
                             const float* __restrict__ Whh) {
    int b  = blockIdx.x;              // 0..191
    int p  = b / 96, r = b % 96;
    int g  = r / 32; r %= 32;
    int jb = r / 8;
    int kc = r % 8;
    const float* W = p ? Whh : Wih;
    unsigned char* hiB = g_wpack + (size_t)b * 8192;
    unsigned char* loB = hiB + 4096;

    int t  = threadIdx.x;             // 128 threads
    int n  = t & 63;
    int kh = t >> 6;
    const float* src = W + (size_t)(g * 256 + jb * 64 + n) * 256 + kc * 32 + kh * 16;
    #pragma unroll
    for (int q4 = 0; q4 < 4; ++q4) {
        float4 v = *(const float4*)(src + q4 * 4);
        int ko = kh * 16 + q4 * 4;
        unsigned off = (unsigned)(((n >> 3) * 4 + (ko >> 3)) * 128 +
                                  (n & 7) * 16 + ((ko >> 2) & 1) * 8);
        u64 hi = pack_hi4(v);
        *(u64*)(hiB + off) = hi;
        *(u64*)(loB + off) = pack_lo4(v, hi);
    }
}

// ---- A prepack: X/H fp32 -> hi/lo bf16 tiles, ldmatrix layout --------------
// tile (p, rb, kc): 16KB = [0,8K) hi, [8K,16K) lo; element (r,k):
// off = ((r>>3)*4 + (k>>3))*128 + (r&7)*16 + ((k>>2)&1)*8  (k in quads of 4)
__global__ void pack_A(const float* __restrict__ X, const float* __restrict__ H,
                       int N, int RB) {
    int rb = blockIdx.x, kc = blockIdx.y, p = blockIdx.z;
    const float* A = p ? H : X;
    unsigned char* dst = (unsigned char*)g_apack +
                         ((size_t)((p * RB + rb) * 8 + kc) << 14);
    int t = threadIdx.x;
    int r = t >> 1, half = t & 1;
    int gm = rb * 128 + r;
    int mi = r >> 3, mr = r & 7;
    const float* src = A + (size_t)gm * 256 + kc * 32;
    #pragma unroll
    for (int qq = 0; qq < 4; ++qq) {
        int q = half * 4 + qq;
        float4 v = (gm < N) ? *(const float4*)(src + q * 4)
                            : make_float4(0.f, 0.f, 0.f, 0.f);
        unsigned off = (unsigned)((mi * 4 + (q >> 1)) * 128 + mr * 16 + (q & 1) * 8);
        u64 hi = pack_hi4(v);
        *(u64*)(dst + off) = hi;
        *(u64*)(dst + 8192 + off) = pack_lo4(v, hi);
    }
}

// ---- main kernel ------------------------------------------------------------
// smem: [0,1024) bias[4][64] | [1024,1152) mask | [1152,2176) wmax[8][32]
//   [4096,...): union of 3 stage bufs (3 x 40960) / epilogue tiles (8 x 17408)
#define SMEM_U       4096
#define STAGE_BYTES  40960          // A hi 8K + A lo 8K + B 3x(4K hi + 4K lo)
#define NSTAGE       3
#define SMEM_TOTAL   (4096 + 8 * 17408)   // 143360 (>= 4096 + 3*40960)

__global__ __launch_bounds__(256, 1)
void gru_mma_kernel(const float* __restrict__ H, const int* __restrict__ divided,
                    const float* __restrict__ bih, const float* __restrict__ bhh,
                    float* __restrict__ out, int N, int RB, int houtoff)
{
    extern __shared__ __align__(1024) unsigned char smem[];
    float* biasS = (float*)smem;
    unsigned char* maskS = smem + 1024;
    float* wmaxS = (float*)(smem + 1152);
    unsigned char* Uc = smem + SMEM_U;
    const uint32_t Ub = smem_u32(smem) + SMEM_U;

    const int tid  = threadIdx.x;
    const int wid  = tid >> 5;
    const int lane = tid & 31;
    const int jb   = blockIdx.x;
    const int j0   = jb * 64;
    const int rby  = blockIdx.y;
    const int row0 = rby * 128;

    const int mh   = wid >> 2;                       // m-half 0/1
    const int st   = ((wid & 3) + 2 * mh) & 3;       // stream 0..3 (SMSP-balanced)
    const int slot = st < 2 ? st : 2;                // B smem slot
    const int cs   = (st == 3) ? 8 : 0;              // active chunk range
    const int ce   = (st == 2) ? 8 : 16;

    // bias[4][64] + mask
    {
        int s = tid >> 6, j = tid & 63, jg = j0 + j;
        float v;
        if      (s == 0) v = bih[jg]       + bhh[jg];
        else if (s == 1) v = bih[256 + jg] + bhh[256 + jg];
        else if (s == 2) v = bih[512 + jg];
        else             v = bhh[512 + jg];
        biasS[tid] = v;
    }
    if (tid < 128) {
        int m = row0 + tid;
        unsigned char msk = 0;
        if (m < N)
            msk = (divided[3 * m] > 0) | (divided[3 * m + 1] > 0) |
                  (divided[3 * m + 2] > 0);
        maskS[tid] = msk;
    }

    float acc[4][8][4];
    #pragma unroll
    for (int a = 0; a < 4; ++a)
        #pragma unroll
        for (int b = 0; b < 8; ++b)
            #pragma unroll
            for (int q = 0; q < 4; ++q) acc[a][b][q] = 0.f;

    // lane constants for ldmatrix
    const int g8 = lane >> 3, lr = lane & 7;
    const uint32_t laneA = (uint32_t)(((g8 & 1) * 4 + (g8 >> 1)) * 128 + lr * 16);
    const uint32_t laneB = (uint32_t)(((g8 >> 1) * 4 + (g8 & 1)) * 128 + lr * 16);

    // ---- cp.async issue for chunk cc into stage sg ----
    auto issue = [&](int cc, int sg) {
        const int p = cc >> 3, kc = cc & 7;
        const uint32_t sdst = Ub + sg * STAGE_BYTES;
        const unsigned char* asrc = (const unsigned char*)g_apack +
            ((size_t)((p * RB + rby) * 8 + kc) << 14);
        #pragma unroll
        for (int i = 0; i < 4; ++i) {
            int line = tid + i * 256;
            cp16(sdst + line * 16, asrc + line * 16);
        }
        #pragma unroll
        for (int g = 0; g < 3; ++g) {
            const unsigned char* bsrc = g_wpack +
                ((size_t)(((p * 3 + g) * 4 + jb) * 8 + kc) << 13);
            #pragma unroll
            for (int i = 0; i < 2; ++i) {
                int line = tid + i * 256;
                cp16(sdst + 16384 + g * 8192 + line * 16, bsrc + line * 16);
            }
        }
    };

    // prologue: fill the pipeline
    #pragma unroll
    for (int cc = 0; cc < NSTAGE; ++cc) {
        issue(cc, cc);
        asm volatile("cp.async.commit_group;");
    }

    int sg = 0;
    for (int c = 0; c < 16; ++c) {
        asm volatile("cp.async.wait_group %0;" :: "n"(NSTAGE - 1));
        __syncthreads();

        // ---- MMA on chunk c (stage sg) ----
        if (c >= cs && c < ce) {
            const uint32_t abh = Ub + sg * STAGE_BYTES;
            const uint32_t abl = abh + 8192;
            const uint32_t bbh = abh + 16384 + slot * 8192;
            const uint32_t bbl = bbh + 4096;
            #pragma unroll
            for (int ks = 0; ks < 2; ++ks) {
                uint32_t ah[4][4], al[4][4];
                #pragma unroll
                for (int mb = 0; mb < 4; ++mb) {
                    uint32_t off = (uint32_t)((mh * 32 + mb * 8 + ks * 2) * 128);
                    ldsm4(abh + off + laneA, ah[mb][0], ah[mb][1], ah[mb][2], ah[mb][3]);
                    ldsm4(abl + off + laneA, al[mb][0], al[mb][1], al[mb][2], al[mb][3]);
                }
                #pragma unroll
                for (int nb2 = 0; nb2 < 4; ++nb2) {
                    uint32_t offb = (uint32_t)((nb2 * 8 + ks * 2) * 128);
                    uint32_t bh[4], bl[4];
                    ldsm4(bbh + offb + laneB, bh[0], bh[1], bh[2], bh[3]);
                    ldsm4(bbl + offb + laneB, bl[0], bl[1], bl[2], bl[3]);
                    #pragma unroll
                    for (int mb = 0; mb < 4; ++mb) {
                        mma16816(acc[mb][nb2 * 2],     ah[mb], bh[0], bh[1]);
                        mma16816(acc[mb][nb2 * 2],     ah[mb], bl[0], bl[1]);
                        mma16816(acc[mb][nb2 * 2],     al[mb], bh[0], bh[1]);
                        mma16816(acc[mb][nb2 * 2 + 1], ah[mb], bh[2], bh[3]);
                        mma16816(acc[mb][nb2 * 2 + 1], ah[mb], bl[2], bl[3]);
                        mma16816(acc[mb][nb2 * 2 + 1], al[mb], bh[2], bh[3]);
                    }
                }
            }
        }
        __syncthreads();
        if (c + NSTAGE < 16) issue(c + NSTAGE, sg);
        asm volatile("cp.async.commit_group;");
        sg = (sg + 1 == NSTAGE) ? 0 : sg + 1;
    }

    // ---- epilogue: dump accum tiles to smem (stride 68) ----
    {
        float* Et = (float*)(Uc + (st * 2 + mh) * 17408);
        int r0l = lane >> 2, c0 = (lane & 3) * 2;
        #pragma unroll
        for (int mb = 0; mb < 4; ++mb)
            #pragma unroll
            for (int nb = 0; nb < 8; ++nb) {
                int r = mb * 16 + r0l, cc = nb * 8 + c0;
                *(float2*)&Et[r * 68 + cc] =
                    make_float2(acc[mb][nb][0], acc[mb][nb][1]);
                *(float2*)&Et[(r + 8) * 68 + cc] =
                    make_float2(acc[mb][nb][2], acc[mb][nb][3]);
            }
    }
    __syncthreads();

    // ---- gate math + masked store + column max ----
    {
        const int row = tid & 127, jh = tid >> 7;
        const int gm = row0 + row;
        const bool valid = gm < N;
        const bool msk = valid && maskS[row];
        const int mh2 = row >> 6, lr2 = row & 63;
        const float* Er  = (float*)(Uc + (0 * 2 + mh2) * 17408) + lr2 * 68 + jh * 32;
        const float* Ez  = (float*)(Uc + (1 * 2 + mh2) * 17408) + lr2 * 68 + jh * 32;
        const float* Eni = (float*)(Uc + (2 * 2 + mh2) * 17408) + lr2 * 68 + jh * 32;
        const float* Enh = (float*)(Uc + (3 * 2 + mh2) * 17408) + lr2 * 68 + jh * 32;
        const float NEG_INF = __int_as_float(0xff800000);

        #pragma unroll
        for (int qb = 0; qb < 8; ++qb) {
            float4 rv  = *(const float4*)(Er  + qb * 4);
            float4 zv  = *(const float4*)(Ez  + qb * 4);
            float4 niv = *(const float4*)(Eni + qb * 4);
            float4 nhv = *(const float4*)(Enh + qb * 4);
            float4 h4 = valid
                ? *(const float4*)&H[(size_t)gm * 256 + j0 + jh * 32 + qb * 4]
                : make_float4(0.f, 0.f, 0.f, 0.f);
            float rr[4] = {rv.x, rv.y, rv.z, rv.w};
            float zz[4] = {zv.x, zv.y, zv.z, zv.w};
            float ni[4] = {niv.x, niv.y, niv.z, niv.w};
            float nh[4] = {nhv.x, nhv.y, nhv.z, nhv.w};
            float hh[4] = {h4.x, h4.y, h4.z, h4.w};
            float o[4];
            #pragma unroll
            for (int e = 0; e < 4; ++e) {
                int jl = jh * 32 + qb * 4 + e;
                float r = 1.f / (1.f + __expf(-(rr[e] + biasS[jl])));
                float z = 1.f / (1.f + __expf(-(zz[e] + biasS[64 + jl])));
                float nn = tanhf(ni[e] + biasS[128 + jl] +
                                 r * (nh[e] + biasS[192 + jl]));
                float hn = (1.f - z) * nn + z * hh[e];
                o[e] = msk ? hn : 0.f;
                float mv = msk ? hn : NEG_INF;
                #pragma unroll
                for (int d = 16; d >= 1; d >>= 1)
                    mv = fmaxf(mv, __shfl_xor_sync(0xffffffffu, mv, d));
                if (lane == 0) wmaxS[wid * 32 + qb * 4 + e] = mv;
            }
            if (valid && houtoff >= 0) {
                *(float4*)&out[(size_t)houtoff + (size_t)gm * 256 + j0 +
                               jh * 32 + qb * 4] = make_float4(o[0], o[1], o[2], o[3]);
            }
        }
    }
    __syncthreads();
    if (tid < 64) {
        int jh = tid >> 5, cl = tid & 31;
        float v =        wmaxS[(jh * 4 + 0) * 32 + cl];
        v = fmaxf(v,     wmaxS[(jh * 4 + 1) * 32 + cl]);
        v = fmaxf(v,     wmaxS[(jh * 4 + 2) * 32 + cl]);
        v = fmaxf(v,     wmaxS[(jh * 4 + 3) * 32 + cl]);
        atomicMax(&g_colmax[j0 + jh * 32 + cl], enc_f(v));
    }
}

__global__ void finalize_kernel(const float* __restrict__ interval,
                                const float* __restrict__ tw,
                                const float* __restrict__ tb,
                                float* __restrict__ out)
{
    int j = threadIdx.x;
    float inv = 1.0f / logf(interval[0] + expf(1.0f));
    float tf  = tanhf(inv * tw[j] + tb[j]);
    out[j] = dec_f(g_colmax[j]) + tf;
}

extern "C" void kernel_launch(void* const* d_in, const int* in_sizes, int n_in,
                              void* d_out, int out_size)
{
    int i_interval = -1, i_co = -1, i_hid = -1, i_div = -1;
    int i_wih = -1, i_whh = -1, i_bih = -1, i_bhh = -1, i_tw = -1, i_tb = -1;
    int c256 = 0;
    for (int i = 0; i < n_in; ++i) {
        int s = in_sizes[i];
        if (s == 1) {
            if (i_interval < 0) i_interval = i;
        } else if (s == 300000) {
            i_div = i;
        } else if (s == 196608) {
            if (i_wih < 0) i_wih = i; else i_whh = i;
        } else if (s == 768) {
            if (i_bih < 0) i_bih = i; else i_bhh = i;
        } else if (s == 256) {
            ++c256;                       // no_emb, unrelated, time_w, time_b
            if (c256 == 3) i_tw = i;
            else if (c256 == 4) i_tb = i;
        } else if (s > 1000000) {         // co_embeddings then hidden_state
            if (i_co < 0) i_co = i; else i_hid = i;
        }
    }

    const float* X   = (const float*)d_in[i_co];
    const float* H   = (const float*)d_in[i_hid];
    const int*   div = (const int*)  d_in[i_div];
    const float* Wih = (const float*)d_in[i_wih];
    const float* Whh = (const float*)d_in[i_whh];
    const float* bih = (const float*)d_in[i_bih];
    const float* bhh = (const float*)d_in[i_bhh];
    const float* itv = (const float*)d_in[i_interval];
    const float* tw  = (const float*)d_in[i_tw];
    const float* tb  = (const float*)d_in[i_tb];
    float* out = (float*)d_out;

    int N = in_sizes[i_co] / 256;
    int RB = (N + 127) / 128;
    if (RB > RB_MAX) RB = RB_MAX;   // dataset: N=100000 -> RB=782
    long long need = 256LL + (long long)N * 256LL;
    int houtoff = ((long long)out_size >= need) ? 256 : -1;

    cudaFuncSetAttribute(gru_mma_kernel,
                         cudaFuncAttributeMaxDynamicSharedMemorySize, SMEM_TOTAL);

    init_kernel<<<1, 256>>>();
    pack_weights<<<192, 128>>>(Wih, Whh);
    dim3 pgrid(RB, 8, 2);
    pack_A<<<pgrid, 256>>>(X, H, N, RB);
    dim3 grid(4, RB);
    gru_mma_kernel<<<grid, 256, SMEM_TOTAL>>>(H, div, bih, bhh, out, N, RB, houtoff);
    finalize_kernel<<<1, 256>>>(itv, tw, tb, out);
}